// round 6
// baseline (speedup 1.0000x reference)
#include <cuda_runtime.h>
#include <cstdint>
#include <cstddef>

#define NB 64
#define NH 12
#define NP 197
#define ND 64
#define TOPK 10
#define NSLOT 7
#define FULLMASK 0xffffffffu
#define NWARPS 16
#define CSLOT 7      // list slots per chain: 5 real (e2..e6) + 2 sentinels
#define LSLOTS 30    // 4*CSLOT + 2 guard rows (covers improbable overrun reads)
#define KSC 1.44269504f   // 1/ln2
#define KOF 23.083f       // shift so key floats are always positive

// Persistent device state (statically initialized; last block resets -> replay-safe)
__device__ double g_acc = 0.0;
__device__ unsigned g_done = 0;

__device__ __forceinline__ float ex2f(float x) {
    float r; asm("ex2.approx.f32 %0, %1;" : "=f"(r) : "f"(x)); return r;
}
// descending compare-exchange (2x IMNMX.U32)
__device__ __forceinline__ void ceu(unsigned& a, unsigned& b) {
    unsigned mx = a > b ? a : b;
    unsigned mn = a > b ? b : a;
    a = mx; b = mn;
}
// Batcher odd-even mergesort for 8 with element 7 = const-min -> 16-CE sort-7.
__device__ __forceinline__ void sort7(unsigned* s) {
    ceu(s[0],s[1]); ceu(s[2],s[3]); ceu(s[4],s[5]);
    ceu(s[0],s[2]); ceu(s[1],s[3]); ceu(s[4],s[6]);
    ceu(s[1],s[2]); ceu(s[5],s[6]);
    ceu(s[0],s[4]); ceu(s[1],s[5]); ceu(s[2],s[6]);
    ceu(s[2],s[4]); ceu(s[3],s[5]);
    ceu(s[1],s[2]); ceu(s[3],s[4]); ceu(s[5],s[6]);
}
// Pad -15.9 -> key float 0.142, below any real logit's key; never tops REDUX.
__device__ __forceinline__ void load_row(float* y, const float* __restrict__ row,
                                         int lane) {
#pragma unroll
    for (int k = 0; k < 6; ++k) y[k] = row[k * 32 + lane];
    y[6] = (lane < NP - 192) ? row[192 + lane] : -15.9f;
}

__global__ void __launch_bounds__(512, 1)
hintop_main(const float* __restrict__ att_s, const float* __restrict__ att_t,
            const float* __restrict__ v_s,   const float* __restrict__ v_t,
            float* __restrict__ out) {
    extern __shared__ float smem[];
    float* vsS = smem;                                   // NP*ND f32 each
    float* vsT = smem + NP * ND;
    unsigned* lists = reinterpret_cast<unsigned*>(smem + 2 * NP * ND);

    const int bh   = blockIdx.x;
    const int warp = threadIdx.x >> 5;
    const int lane = threadIdx.x & 31;

    {   // fill both v tiles (f32, vectorized, 512 threads)
        const float4* a4 = reinterpret_cast<const float4*>(v_s + (size_t)bh * NP * ND);
        const float4* b4 = reinterpret_cast<const float4*>(v_t + (size_t)bh * NP * ND);
        float4* s4 = reinterpret_cast<float4*>(vsS);
        float4* t4 = reinterpret_cast<float4*>(vsT);
        for (int i = threadIdx.x; i < NP * ND / 4; i += 512) {
            s4[i] = a4[i];
            t4[i] = b4[i];
        }
    }
    const int lb = warp * (LSLOTS * 32) + lane;          // per-warp per-lane base
#pragma unroll
    for (int c = 0; c < 4; ++c) {                        // zero sentinels once
        lists[lb + (c * CSLOT + 5) * 32] = 0u;
        lists[lb + (c * CSLOT + 6) * 32] = 0u;
    }
    __syncthreads();

    const float* aS = att_s + (size_t)bh * NP * NP;
    const float* aT = att_t + (size_t)bh * NP * NP;
    const float2* __restrict__ v2S = reinterpret_cast<const float2*>(vsS) + lane;
    const float2* __restrict__ v2T = reinterpret_cast<const float2*>(vsT) + lane;

    // per-warp contiguous row chunk [s0, s1), 12 or 13 rows; paired (s0+j, s0+half+j)
    const int s0   = (warp * NP) >> 4;
    const int s1   = ((warp + 1) * NP) >> 4;
    const int cnt  = s1 - s0;
    const int half = (cnt + 1) >> 1;

    float lsum = 0.f;
    float cy[4][NSLOT], ny[4][NSLOT];
    load_row(cy[0], aS + (size_t)s0 * NP, lane);
    load_row(cy[1], aT + (size_t)s0 * NP, lane);
    load_row(cy[2], aS + (size_t)(s0 + half) * NP, lane);
    load_row(cy[3], aT + (size_t)(s0 + half) * NP, lane);

    for (int j = 0; j < half; ++j) {
        const bool maskB = (j + half < cnt);             // 2nd row valid?

        // ---- keys (FFMA folds 1/ln2; positive => bit order == value order),
        //      sort each chain's 7 descending, spill e2..e6 to smem list
        unsigned sk[4][NSLOT];
#pragma unroll
        for (int c = 0; c < 4; ++c) {
#pragma unroll
            for (int k = 0; k < NSLOT; ++k) {
                unsigned idx = (unsigned)(k * 32 + lane);
                sk[c][k] = (__float_as_uint(fmaf(cy[c][k], KSC, KOF)) & 0xFFFFFF00u) | idx;
            }
            sort7(sk[c]);
#pragma unroll
            for (int e = 0; e < 5; ++e) lists[lb + (c * CSLOT + e) * 32] = sk[c][2 + e];
        }

        // ---- prefetch next row pair (clamped; results discarded past the end)
        {
            int an = s0 + j + 1;        if (an > NP - 1) an = NP - 1;
            int bn = s0 + half + j + 1; if (bn > NP - 1) bn = NP - 1;
            load_row(ny[0], aS + (size_t)an * NP, lane);
            load_row(ny[1], aT + (size_t)an * NP, lane);
            load_row(ny[2], aS + (size_t)bn * NP, lane);
            load_row(ny[3], aT + (size_t)bn * NP, lane);
        }

        // ---- pop top-10 on 4 independent REDUX chains (ILP hides latency)
        unsigned cand[4], nxt[4];
        int lp[4];
        float ax[4], ay[4], ws[4];
#pragma unroll
        for (int c = 0; c < 4; ++c) {
            cand[c] = sk[c][0];
            nxt[c]  = sk[c][1];
            lp[c]   = lb + (c * CSLOT) * 32;
            ax[c] = 0.f; ay[c] = 0.f; ws[c] = 0.f;
        }
#pragma unroll
        for (int it = 0; it < TOPK; ++it) {
#pragma unroll
            for (int c = 0; c < 4; ++c) {
                unsigned wm = __reduce_max_sync(FULLMASK, cand[c]);
                if (it < TOPK - 1) {
                    bool own = (cand[c] == wm);          // unique keys -> one owner
                    cand[c] = own ? nxt[c] : cand[c];
                    if (own) { nxt[c] = lists[lp[c]]; lp[c] += 32; }
                }
                // w = 2^(key bits as float); idx-bit noise <= 3.4e-4 rel; the
                // KOF shift and 2^ vs e^ base cancel in the normalizer.
                float w = ex2f(__uint_as_float(wm));
                unsigned e = wm & 0xFFu;                 // element/v-row index
                const float2 vv = ((c & 1) ? v2T : v2S)[e * 32];
                ax[c] = fmaf(w, vv.x, ax[c]);
                ay[c] = fmaf(w, vv.y, ay[c]);
                ws[c] += w;
            }
        }

        // ---- normalize, S-T diff, accumulate MSE partials
        float i0 = __fdividef(1.f, ws[0]);
        float i1 = __fdividef(1.f, ws[1]);
        float dx = ax[0] * i0 - ax[1] * i1;
        float dy = ay[0] * i0 - ay[1] * i1;
        lsum = fmaf(dx, dx, lsum);
        lsum = fmaf(dy, dy, lsum);
        if (maskB) {
            float i2 = __fdividef(1.f, ws[2]);
            float i3 = __fdividef(1.f, ws[3]);
            float ex = ax[2] * i2 - ax[3] * i3;
            float ey = ay[2] * i2 - ay[3] * i3;
            lsum = fmaf(ex, ex, lsum);
            lsum = fmaf(ey, ey, lsum);
        }

#pragma unroll
        for (int c = 0; c < 4; ++c)
#pragma unroll
            for (int k = 0; k < NSLOT; ++k) cy[c][k] = ny[c][k];
    }

    // warp reduce -> block reduce -> one double atomic; last block finalizes.
#pragma unroll
    for (int off = 16; off; off >>= 1) lsum += __shfl_xor_sync(FULLMASK, lsum, off);

    __shared__ float wsum_sh[NWARPS];
    if (lane == 0) wsum_sh[warp] = lsum;
    __syncthreads();
    if (threadIdx.x == 0) {
        float t = 0.f;
#pragma unroll
        for (int w = 0; w < NWARPS; ++w) t += wsum_sh[w];
        atomicAdd(&g_acc, (double)t);
        __threadfence();
        unsigned ticket = atomicAdd(&g_done, 1);
        if (ticket == (unsigned)(gridDim.x - 1)) {
            __threadfence();
            double total = atomicAdd(&g_acc, 0.0);
            out[0] = (float)(total / (double)((size_t)NB * NH * NP * ND));
            g_acc = 0.0;                                 // reset for graph replay
            g_done = 0;
            __threadfence();
        }
    }
}

extern "C" void kernel_launch(void* const* d_in, const int* in_sizes, int n_in,
                              void* d_out, int out_size) {
    const float* att_s = (const float*)d_in[0];
    const float* att_t = (const float*)d_in[1];
    const float* v_s   = (const float*)d_in[2];
    const float* v_t   = (const float*)d_in[3];

    // 100,864 (two f32 v tiles) + 61,440 (lists) = 162,304 B -> 1 CTA/SM
    const int smem_bytes = 2 * NP * ND * 4 + NWARPS * LSLOTS * 32 * 4;
    cudaFuncSetAttribute(hintop_main, cudaFuncAttributeMaxDynamicSharedMemorySize,
                         smem_bytes);

    hintop_main<<<NB * NH, 512, smem_bytes>>>(att_s, att_t, v_s, v_t, (float*)d_out);
}

// round 7
// speedup vs baseline: 1.0862x; 1.0862x over previous
#include <cuda_runtime.h>
#include <cstdint>
#include <cstddef>

#define NB 64
#define NH 12
#define NP 197
#define ND 64
#define TOPK 10
#define NSLOT 7
#define FULLMASK 0xffffffffu
#define LSLOTS 12    // per-warp per-lane slots: S e2..e6 in 0..4, sentinels 5..6, T e2..e6 in 11..7
#define KSC 1.44269504f   // 1/ln2 (folded so decode is a bare ex2.approx)
#define KOF 23.083f       // shift keeps key floats positive -> bit order == value order

// Persistent device state (statically initialized; last block resets -> replay-safe)
__device__ double g_acc = 0.0;
__device__ unsigned g_done = 0;

__device__ __forceinline__ float ex2f(float x) {
    float r; asm("ex2.approx.f32 %0, %1;" : "=f"(r) : "f"(x)); return r;
}
// descending compare-exchange (2x IMNMX.U32)
__device__ __forceinline__ void ceu(unsigned& a, unsigned& b) {
    unsigned mx = a > b ? a : b;
    unsigned mn = a > b ? b : a;
    a = mx; b = mn;
}
// Batcher odd-even mergesort for 8 with element 7 = const-min -> 16-CE sort-7.
__device__ __forceinline__ void sort7(unsigned* s) {
    ceu(s[0],s[1]); ceu(s[2],s[3]); ceu(s[4],s[5]);
    ceu(s[0],s[2]); ceu(s[1],s[3]); ceu(s[4],s[6]);
    ceu(s[1],s[2]); ceu(s[5],s[6]);
    ceu(s[0],s[4]); ceu(s[1],s[5]); ceu(s[2],s[6]);
    ceu(s[2],s[4]); ceu(s[3],s[5]);
    ceu(s[1],s[2]); ceu(s[3],s[4]); ceu(s[5],s[6]);
}
// Pad -15.9 -> key float 0.146 > 0, below any real logit's key; never tops REDUX.
__device__ __forceinline__ void load_row(float* y, const float* __restrict__ row,
                                         int lane) {
#pragma unroll
    for (int k = 0; k < 6; ++k) y[k] = row[k * 32 + lane];
    y[6] = (lane < NP - 192) ? row[192 + lane] : -15.9f;
}

// One full row-pair step: keys/sort/spill from (cS,cT), prefetch row p+8 into
// (nS,nT) so LDG latency overlaps the pop phase, then pop top-10 on two
// independent REDUX chains and accumulate the MSE partial.
__device__ __forceinline__ void step(
    float (&cS)[NSLOT], float (&cT)[NSLOT],
    float (&nS)[NSLOT], float (&nT)[NSLOT],
    int p, const float* __restrict__ aS, const float* __restrict__ aT,
    int lane, unsigned* __restrict__ lists, int lb,
    const float2* __restrict__ v2S, const float2* __restrict__ v2T,
    float& lsum)
{
    // ---- keys: FFMA folds 1/ln2; positive => bit order == value order
    unsigned sS[NSLOT], sT[NSLOT];
#pragma unroll
    for (int k = 0; k < NSLOT; ++k) {
        unsigned idx = (unsigned)(k * 32 + lane);
        sS[k] = (__float_as_uint(fmaf(cS[k], KSC, KOF)) & 0xFFFFFF00u) | idx;
        sT[k] = (__float_as_uint(fmaf(cT[k], KSC, KOF)) & 0xFFFFFF00u) | idx;
    }
    sort7(sS);
    sort7(sT);

    // ---- spill entries 2..6; S ascending slots 0..4, T descending 11..7
#pragma unroll
    for (int j = 0; j < 5; ++j) {
        lists[lb + j * 32] = sS[2 + j];
        lists[lb + (11 - j) * 32] = sT[2 + j];
    }

    // ---- prefetch next row pair (clamped; results discarded past the end)
    {
        int pl = p + 8;
        if (pl > NP - 1) pl = NP - 1;
        load_row(nS, aS + (size_t)pl * NP, lane);
        load_row(nT, aT + (size_t)pl * NP, lane);
    }

    // ---- pop top-10 per chain; two independent REDUX chains for ILP
    unsigned candS = sS[0], nextS = sS[1];
    unsigned candT = sT[0], nextT = sT[1];
    int lpS = lb;                 // reads slots 0..4 then sentinels 5,6
    int lpT = lb + 11 * 32;       // reads slots 11..7 then sentinels 6,5
    float2 accS = make_float2(0.f, 0.f), accT = make_float2(0.f, 0.f);
    float wsS = 0.f, wsT = 0.f;
#pragma unroll
    for (int it = 0; it < TOPK; ++it) {
        unsigned wmS = __reduce_max_sync(FULLMASK, candS);
        unsigned wmT = __reduce_max_sync(FULLMASK, candT);

        if (it < TOPK - 1) {
            bool oS = (candS == wmS);            // unique keys -> one owner
            candS = oS ? nextS : candS;
            if (oS) { nextS = lists[lpS]; lpS += 32; }   // refill off-chain
            bool oT = (candT == wmT);
            candT = oT ? nextT : candT;
            if (oT) { nextT = lists[lpT]; lpT -= 32; }
        }

        // w = 2^(key bits); idx-bit noise <= 3.4e-4 rel; KOF and base-2 cancel
        // in the normalizer. Decode: one MUFU.EX2, no mask, no FMUL.
        float wS = ex2f(__uint_as_float(wmS));
        float wT = ex2f(__uint_as_float(wmT));
        unsigned iS = wmS & 0xFFu;               // element/v-row index
        unsigned iT = wmT & 0xFFu;
        float2 vvS = v2S[iS * 32];
        float2 vvT = v2T[iT * 32];
        accS.x = fmaf(wS, vvS.x, accS.x);
        accS.y = fmaf(wS, vvS.y, accS.y);
        wsS += wS;
        accT.x = fmaf(wT, vvT.x, accT.x);
        accT.y = fmaf(wT, vvT.y, accT.y);
        wsT += wT;
    }

    float invS = __fdividef(1.0f, wsS);
    float invT = __fdividef(1.0f, wsT);
    float dx = accS.x * invS - accT.x * invT;
    float dy = accS.y * invS - accT.y * invT;
    lsum = fmaf(dx, dx, lsum);
    lsum = fmaf(dy, dy, lsum);
}

__global__ void __launch_bounds__(256, 2)
hintop_main(const float* __restrict__ att_s, const float* __restrict__ att_t,
            const float* __restrict__ v_s,   const float* __restrict__ v_t,
            float* __restrict__ out) {
    extern __shared__ float smem[];
    float* vsS = smem;                                   // NP*ND f32 each
    float* vsT = smem + NP * ND;
    unsigned* lists = reinterpret_cast<unsigned*>(smem + 2 * NP * ND);

    const int bh   = blockIdx.x;
    const int warp = threadIdx.x >> 5;
    const int lane = threadIdx.x & 31;

    {   // fill both v tiles (f32, vectorized)
        const float4* a4 = reinterpret_cast<const float4*>(v_s + (size_t)bh * NP * ND);
        const float4* b4 = reinterpret_cast<const float4*>(v_t + (size_t)bh * NP * ND);
        float4* s4 = reinterpret_cast<float4*>(vsS);
        float4* t4 = reinterpret_cast<float4*>(vsT);
        for (int i = threadIdx.x; i < NP * ND / 4; i += 256) {
            s4[i] = a4[i];
            t4[i] = b4[i];
        }
    }
    // per-warp per-lane list base; zero the two shared sentinel slots once
    const int lb = warp * (LSLOTS * 32) + lane;
    lists[lb + 5 * 32] = 0u;
    lists[lb + 6 * 32] = 0u;
    __syncthreads();

    const float* aS = att_s + (size_t)bh * NP * NP;
    const float* aT = att_t + (size_t)bh * NP * NP;
    const float2* __restrict__ v2S = reinterpret_cast<const float2*>(vsS) + lane;
    const float2* __restrict__ v2T = reinterpret_cast<const float2*>(vsT) + lane;

    float lsum = 0.f;
    int p = warp;
    float cS[NSLOT], cT[NSLOT], nS[NSLOT], nT[NSLOT];
    load_row(cS, aS + (size_t)p * NP, lane);
    load_row(cT, aT + (size_t)p * NP, lane);

    // two-phase unroll: buffer roles alternate -> no register copy per iter
    while (p < NP) {
        step(cS, cT, nS, nT, p, aS, aT, lane, lists, lb, v2S, v2T, lsum);
        p += 8;
        if (p >= NP) break;
        step(nS, nT, cS, cT, p, aS, aT, lane, lists, lb, v2S, v2T, lsum);
        p += 8;
    }

    // warp reduce -> block reduce -> one double atomic; last block finalizes.
#pragma unroll
    for (int off = 16; off; off >>= 1) lsum += __shfl_xor_sync(FULLMASK, lsum, off);

    __shared__ float wsum_sh[8];
    if (lane == 0) wsum_sh[warp] = lsum;
    __syncthreads();
    if (threadIdx.x == 0) {
        float t = 0.f;
#pragma unroll
        for (int w = 0; w < 8; ++w) t += wsum_sh[w];
        atomicAdd(&g_acc, (double)t);
        __threadfence();
        unsigned ticket = atomicAdd(&g_done, 1);
        if (ticket == (unsigned)(gridDim.x - 1)) {
            __threadfence();
            double total = atomicAdd(&g_acc, 0.0);
            out[0] = (float)(total / (double)((size_t)NB * NH * NP * ND));
            g_acc = 0.0;                                 // reset for graph replay
            g_done = 0;
            __threadfence();
        }
    }
}

extern "C" void kernel_launch(void* const* d_in, const int* in_sizes, int n_in,
                              void* d_out, int out_size) {
    const float* att_s = (const float*)d_in[0];
    const float* att_t = (const float*)d_in[1];
    const float* v_s   = (const float*)d_in[2];
    const float* v_t   = (const float*)d_in[3];

    const int smem_bytes = 2 * NP * ND * 4 + 8 * LSLOTS * 32 * 4;   // 113,152 B
    cudaFuncSetAttribute(hintop_main, cudaFuncAttributeMaxDynamicSharedMemorySize,
                         smem_bytes);

    hintop_main<<<NB * NH, 256, smem_bytes>>>(att_s, att_t, v_s, v_t, (float*)d_out);
}

// round 9
// speedup vs baseline: 1.1965x; 1.1015x over previous
#include <cuda_runtime.h>
#include <cstdint>
#include <cstddef>

#define NB 64
#define NH 12
#define NP 197
#define ND 64
#define TOPK 10
#define NSLOT 7
#define FULLMASK 0xffffffffu
#define LSLOTS 12    // per-warp per-lane slots: S e2..e6 in 0..4, sentinels 5..6, T e2..e6 in 11..7
#define KSC 1.44269504f   // 1/ln2 (folded so pop decode is a bare ex2.approx)
#define KOF 23.083f       // shift keeps key floats positive -> bit order == value order

// Persistent device state (statically initialized; last block resets -> replay-safe)
__device__ double g_acc = 0.0;
__device__ unsigned g_done = 0;

__device__ __forceinline__ float ex2f(float x) {
    float r; asm("ex2.approx.f32 %0, %1;" : "=f"(r) : "f"(x)); return r;
}
// descending compare-exchange (2x IMNMX.U32)
__device__ __forceinline__ void ceu(unsigned& a, unsigned& b) {
    unsigned mx = a > b ? a : b;
    unsigned mn = a > b ? b : a;
    a = mx; b = mn;
}
// Batcher odd-even mergesort for 8 with element 7 = const-min -> 16-CE sort-7.
__device__ __forceinline__ void sort7(unsigned* s) {
    ceu(s[0],s[1]); ceu(s[2],s[3]); ceu(s[4],s[5]);
    ceu(s[0],s[2]); ceu(s[1],s[3]); ceu(s[4],s[6]);
    ceu(s[1],s[2]); ceu(s[5],s[6]);
    ceu(s[0],s[4]); ceu(s[1],s[5]); ceu(s[2],s[6]);
    ceu(s[2],s[4]); ceu(s[3],s[5]);
    ceu(s[1],s[2]); ceu(s[3],s[4]); ceu(s[5],s[6]);
}

// Pad -15.9 -> key float ~0.15 > 0, below any real logit's key; never tops REDUX.
__device__ __forceinline__ void load_row(float* y, const float* __restrict__ row,
                                         int lane) {
#pragma unroll
    for (int k = 0; k < 6; ++k) y[k] = row[k * 32 + lane];
    y[6] = (lane < NP - 192) ? row[192 + lane] : -15.9f;
}

__global__ void __launch_bounds__(256, 2)
hintop_main(const float* __restrict__ att_s, const float* __restrict__ att_t,
            const float* __restrict__ v_s,   const float* __restrict__ v_t,
            float* __restrict__ out) {
    extern __shared__ float smem[];
    float* vsS = smem;                                   // NP*ND f32 each
    float* vsT = smem + NP * ND;
    unsigned* lists = reinterpret_cast<unsigned*>(smem + 2 * NP * ND);

    const int bh   = blockIdx.x;
    const int warp = threadIdx.x >> 5;
    const int lane = threadIdx.x & 31;

    {   // fill both v tiles (f32, vectorized)
        const float4* a4 = reinterpret_cast<const float4*>(v_s + (size_t)bh * NP * ND);
        const float4* b4 = reinterpret_cast<const float4*>(v_t + (size_t)bh * NP * ND);
        float4* s4 = reinterpret_cast<float4*>(vsS);
        float4* t4 = reinterpret_cast<float4*>(vsT);
        for (int i = threadIdx.x; i < NP * ND / 4; i += 256) {
            s4[i] = a4[i];
            t4[i] = b4[i];
        }
    }
    // per-warp per-lane list base; zero the two shared sentinel slots once
    const int lb = warp * (LSLOTS * 32) + lane;
    lists[lb + 5 * 32] = 0u;
    lists[lb + 6 * 32] = 0u;
    __syncthreads();

    const float* aS = att_s + (size_t)bh * NP * NP;
    const float* aT = att_t + (size_t)bh * NP * NP;
    const float2* __restrict__ v2S = reinterpret_cast<const float2*>(vsS) + lane;
    const float2* __restrict__ v2T = reinterpret_cast<const float2*>(vsT) + lane;

    float lsum = 0.f;
    int p = warp;
    float cS[NSLOT], cT[NSLOT], nS[NSLOT], nT[NSLOT];
    if (p < NP) {
        load_row(cS, aS + (size_t)p * NP, lane);
        load_row(cT, aT + (size_t)p * NP, lane);
    }

    while (p < NP) {
        const int pn = p + 8;

        // ---- keys: FFMA folds 1/ln2; positive => bit order == value order
        unsigned sS[NSLOT], sT[NSLOT];
#pragma unroll
        for (int k = 0; k < NSLOT; ++k) {
            unsigned idx = (unsigned)(k * 32 + lane);
            sS[k] = (__float_as_uint(fmaf(cS[k], KSC, KOF)) & 0xFFFFFF00u) | idx;
            sT[k] = (__float_as_uint(fmaf(cT[k], KSC, KOF)) & 0xFFFFFF00u) | idx;
        }
        sort7(sS);
        sort7(sT);

        // ---- spill entries 2..6; S ascending slots 0..4, T descending 11..7
#pragma unroll
        for (int j = 0; j < 5; ++j) {
            lists[lb + j * 32] = sS[2 + j];
            lists[lb + (11 - j) * 32] = sT[2 + j];
        }

        // ---- prefetch next row pair (clamped; discarded at loop exit)
        {
            int pl = pn < NP - 1 ? pn : NP - 1;
            load_row(nS, aS + (size_t)pl * NP, lane);
            load_row(nT, aT + (size_t)pl * NP, lane);
        }

        // ---- pop top-10 per chain; two independent REDUX chains for ILP
        unsigned candS = sS[0], nextS = sS[1];
        unsigned candT = sT[0], nextT = sT[1];
        int lpS = lb;                 // reads slots 0..4 then sentinels 5,6
        int lpT = lb + 11 * 32;       // reads slots 11..7 then sentinels 6,5
        float2 accS = make_float2(0.f, 0.f), accT = make_float2(0.f, 0.f);
        float wsS = 0.f, wsT = 0.f;
#pragma unroll
        for (int it = 0; it < TOPK; ++it) {
            unsigned wmS = __reduce_max_sync(FULLMASK, candS);
            unsigned wmT = __reduce_max_sync(FULLMASK, candT);

            if (it < TOPK - 1) {
                bool oS = (candS == wmS);         // unique keys -> one owner
                candS = oS ? nextS : candS;
                if (oS) { nextS = lists[lpS]; lpS += 32; }   // refill off-chain
                bool oT = (candT == wmT);
                candT = oT ? nextT : candT;
                if (oT) { nextT = lists[lpT]; lpT -= 32; }
            }

            // w = 2^(key bits as float): one MUFU.EX2, no mask, no FMUL.
            // idx-bit noise <= 3.4e-4 rel; KOF and base-2 cancel in normalizer.
            float wS = ex2f(__uint_as_float(wmS));
            float wT = ex2f(__uint_as_float(wmT));
            unsigned iS = wmS & 0xFFu;
            unsigned iT = wmT & 0xFFu;
            float2 vvS = v2S[iS * 32];
            float2 vvT = v2T[iT * 32];
            accS.x = fmaf(wS, vvS.x, accS.x);
            accS.y = fmaf(wS, vvS.y, accS.y);
            wsS += wS;
            accT.x = fmaf(wT, vvT.x, accT.x);
            accT.y = fmaf(wT, vvT.y, accT.y);
            wsT += wT;
        }

        float invS = __fdividef(1.0f, wsS);
        float invT = __fdividef(1.0f, wsT);
        float dx = accS.x * invS - accT.x * invT;
        float dy = accS.y * invS - accT.y * invT;
        lsum = fmaf(dx, dx, lsum);
        lsum = fmaf(dy, dy, lsum);

        p = pn;
#pragma unroll
        for (int k = 0; k < NSLOT; ++k) { cS[k] = nS[k]; cT[k] = nT[k]; }
    }

    // warp reduce -> block reduce -> one double atomic; last block finalizes.
#pragma unroll
    for (int off = 16; off; off >>= 1) lsum += __shfl_xor_sync(FULLMASK, lsum, off);

    __shared__ float wsum_sh[8];
    if (lane == 0) wsum_sh[warp] = lsum;
    __syncthreads();
    if (threadIdx.x == 0) {
        float t = 0.f;
#pragma unroll
        for (int w = 0; w < 8; ++w) t += wsum_sh[w];
        atomicAdd(&g_acc, (double)t);
        __threadfence();
        unsigned ticket = atomicAdd(&g_done, 1);
        if (ticket == (unsigned)(gridDim.x - 1)) {
            __threadfence();
            double total = atomicAdd(&g_acc, 0.0);
            out[0] = (float)(total / (double)((size_t)NB * NH * NP * ND));
            g_acc = 0.0;                                 // reset for graph replay
            g_done = 0;
            __threadfence();
        }
    }
}

extern "C" void kernel_launch(void* const* d_in, const int* in_sizes, int n_in,
                              void* d_out, int out_size) {
    const float* att_s = (const float*)d_in[0];
    const float* att_t = (const float*)d_in[1];
    const float* v_s   = (const float*)d_in[2];
    const float* v_t   = (const float*)d_in[3];

    const int smem_bytes = 2 * NP * ND * 4 + 8 * LSLOTS * 32 * 4;   // 113,152 B
    cudaFuncSetAttribute(hintop_main, cudaFuncAttributeMaxDynamicSharedMemorySize,
                         smem_bytes);

    hintop_main<<<NB * NH, 256, smem_bytes>>>(att_s, att_t, v_s, v_t, (float*)d_out);
}